// round 1
// baseline (speedup 1.0000x reference)
#include <cuda_runtime.h>

#define D 8192
#define THREADS 256
#define PER_THREAD (D / THREADS)        // 32 scalars per thread
#define V4_PER_THREAD (PER_THREAD / 4)  // 8 float4 per thread
#define NWARPS (THREADS / 32)
#define BUF 2048                        // candidate buffer (floats)

__global__ __launch_bounds__(THREADS)
void sparsemax_kernel(const float* __restrict__ x, float* __restrict__ out) {
    __shared__ float srow[D];            // 32 KB: staged row
    __shared__ float sbuf[BUF];          // 8 KB: candidates > max-1
    __shared__ float swarp[NWARPS];      // max reduction scratch
    __shared__ float sredf[NWARPS];      // fallback sum scratch
    __shared__ int   sredk[NWARPS];      // fallback count scratch
    __shared__ int   s_cnt;
    __shared__ float s_max;
    __shared__ float s_tau;
    __shared__ int   s_k;

    const int row = blockIdx.x;
    const int tid = threadIdx.x;
    const float4* __restrict__ xin  = reinterpret_cast<const float4*>(x + (size_t)row * D);
    float4* __restrict__       xout = reinterpret_cast<float4*>(out + (size_t)row * D);
    float4* __restrict__       srow4 = reinterpret_cast<float4*>(srow);

    if (tid == 0) s_cnt = 0;

    // ---- Pass 1: load row to SMEM (float4) + thread-local max ----
    float m = -__int_as_float(0x7f800000);  // -inf
    #pragma unroll
    for (int i = 0; i < V4_PER_THREAD; i++) {
        int idx = tid + i * THREADS;
        float4 v = xin[idx];
        srow4[idx] = v;
        m = fmaxf(m, fmaxf(fmaxf(v.x, v.y), fmaxf(v.z, v.w)));
    }
    // block reduce max
    #pragma unroll
    for (int o = 16; o > 0; o >>= 1)
        m = fmaxf(m, __shfl_xor_sync(0xffffffffu, m, o));
    if ((tid & 31) == 0) swarp[tid >> 5] = m;
    __syncthreads();
    if (tid < 32) {
        float mm = (tid < NWARPS) ? swarp[tid] : -__int_as_float(0x7f800000);
        #pragma unroll
        for (int o = 16; o > 0; o >>= 1)
            mm = fmaxf(mm, __shfl_xor_sync(0xffffffffu, mm, o));
        if (tid == 0) s_max = mm;
    }
    __syncthreads();
    const float thr = s_max - 1.0f;   // valid lower bound on tau*

    // ---- Pass 2: gather candidates {x > max-1} into sbuf ----
    #pragma unroll
    for (int i = 0; i < PER_THREAD; i++) {
        float v = srow[tid + i * THREADS];   // conflict-free strided
        if (v > thr) {
            int p = atomicAdd(&s_cnt, 1);
            if (p < BUF) sbuf[p] = v;
        }
    }
    __syncthreads();
    const int cnt = s_cnt;

    if (cnt <= BUF) {
        // ---- Michelot fixed-point on the tiny candidate set (warp 0) ----
        if (tid < 32) {
            float tau = thr;
            int prev = -1;
            for (int it = 0; it < cnt + 2; it++) {
                float s = 0.0f; int k = 0;
                for (int j = tid; j < cnt; j += 32) {
                    float v = sbuf[j];
                    if (v > tau) { s += v; k++; }
                }
                #pragma unroll
                for (int o = 16; o > 0; o >>= 1) {
                    s += __shfl_xor_sync(0xffffffffu, s, o);
                    k += __shfl_xor_sync(0xffffffffu, k, o);
                }
                float ntau = (s - 1.0f) / (float)k;
                tau = ntau;
                if (k == prev) break;   // active set stable -> fixed point
                prev = k;
            }
            if (tid == 0) s_tau = tau;
        }
        __syncthreads();
    } else {
        // ---- Fallback: block-wide Michelot over the full SMEM row ----
        float tau = thr;
        int prev = -1;
        for (int it = 0; it < D + 2; it++) {
            float s = 0.0f; int k = 0;
            #pragma unroll
            for (int i = 0; i < PER_THREAD; i++) {
                float v = srow[tid + i * THREADS];
                if (v > tau) { s += v; k++; }
            }
            #pragma unroll
            for (int o = 16; o > 0; o >>= 1) {
                s += __shfl_xor_sync(0xffffffffu, s, o);
                k += __shfl_xor_sync(0xffffffffu, k, o);
            }
            if ((tid & 31) == 0) { sredf[tid >> 5] = s; sredk[tid >> 5] = k; }
            __syncthreads();
            if (tid == 0) {
                float S = 0.0f; int K = 0;
                #pragma unroll
                for (int w = 0; w < NWARPS; w++) { S += sredf[w]; K += sredk[w]; }
                s_tau = (S - 1.0f) / (float)K;
                s_k = K;
            }
            __syncthreads();
            tau = s_tau;
            int K = s_k;
            if (K == prev) break;    // uniform across block
            prev = K;
        }
        __syncthreads();
    }

    // ---- Pass 3: write relu(x - tau), vectorized from SMEM ----
    const float tau = s_tau;
    #pragma unroll
    for (int i = 0; i < V4_PER_THREAD; i++) {
        int idx = tid + i * THREADS;
        float4 v = srow4[idx];
        v.x = fmaxf(v.x - tau, 0.0f);
        v.y = fmaxf(v.y - tau, 0.0f);
        v.z = fmaxf(v.z - tau, 0.0f);
        v.w = fmaxf(v.w - tau, 0.0f);
        xout[idx] = v;
    }
}

extern "C" void kernel_launch(void* const* d_in, const int* in_sizes, int n_in,
                              void* d_out, int out_size) {
    const float* x = (const float*)d_in[0];
    float* out = (float*)d_out;
    const int rows = in_sizes[0] / D;   // 8192
    sparsemax_kernel<<<rows, THREADS>>>(x, out);
}

// round 2
// speedup vs baseline: 1.2089x; 1.2089x over previous
#include <cuda_runtime.h>

#define D 8192
#define THREADS 512
#define PER_THREAD (D / THREADS)        // 16 scalars per thread
#define NWARPS (THREADS / 32)           // 16
#define BUF 1024                        // candidate buffer (floats)

__global__ __launch_bounds__(THREADS, 3)
void sparsemax_kernel(const float* __restrict__ x, float* __restrict__ out) {
    __shared__ float sbuf[BUF];          // 4 KB: candidates > max-1
    __shared__ float swarp[NWARPS];      // block max scratch
    __shared__ float sredf[NWARPS];      // fallback sum scratch
    __shared__ int   sredk[NWARPS];      // fallback count scratch
    __shared__ int   s_cnt;
    __shared__ float s_tau;
    __shared__ int   s_k;

    const int row = blockIdx.x;
    const int tid = threadIdx.x;
    const int lid = tid & 31;
    const float4* __restrict__ xin  = reinterpret_cast<const float4*>(x + (size_t)row * D);
    float4* __restrict__       xout = reinterpret_cast<float4*>(out + (size_t)row * D);

    if (tid == 0) s_cnt = 0;

    // ---- Pass 1: load 16 values into registers (4x LDG.128, all independent) ----
    float4 v0 = xin[tid];
    float4 v1 = xin[tid + THREADS];
    float4 v2 = xin[tid + 2 * THREADS];
    float4 v3 = xin[tid + 3 * THREADS];

    float m = fmaxf(fmaxf(fmaxf(v0.x, v0.y), fmaxf(v0.z, v0.w)),
                    fmaxf(fmaxf(v1.x, v1.y), fmaxf(v1.z, v1.w)));
    m = fmaxf(m, fmaxf(fmaxf(v2.x, v2.y), fmaxf(v2.z, v2.w)));
    m = fmaxf(m, fmaxf(fmaxf(v3.x, v3.y), fmaxf(v3.z, v3.w)));

    // warp-reduce max
    #pragma unroll
    for (int o = 16; o > 0; o >>= 1)
        m = fmaxf(m, __shfl_xor_sync(0xffffffffu, m, o));
    if (lid == 0) swarp[tid >> 5] = m;
    __syncthreads();   // also covers s_cnt = 0

    // every warp redundantly reduces the 16 warp-maxes (no second barrier)
    float mm = swarp[lid & (NWARPS - 1)];
    #pragma unroll
    for (int o = NWARPS / 2; o > 0; o >>= 1)
        mm = fmaxf(mm, __shfl_xor_sync(0xffffffffu, mm, o));
    const float thr = mm - 1.0f;     // valid lower bound on tau*

    // ---- Pass 2: gather candidates {x > thr} from registers (rare) ----
    {
        float vals[PER_THREAD] = {v0.x, v0.y, v0.z, v0.w,
                                  v1.x, v1.y, v1.z, v1.w,
                                  v2.x, v2.y, v2.z, v2.w,
                                  v3.x, v3.y, v3.z, v3.w};
        #pragma unroll
        for (int i = 0; i < PER_THREAD; i++) {
            if (vals[i] > thr) {
                int p = atomicAdd(&s_cnt, 1);
                if (p < BUF) sbuf[p] = vals[i];
            }
        }
    }
    __syncthreads();
    const int cnt = s_cnt;

    if (cnt <= BUF) {
        // ---- Michelot fixed-point on the tiny candidate set (warp 0) ----
        if (tid < 32) {
            float tau = thr;
            int prev = -1;
            for (int it = 0; it < cnt + 2; it++) {
                float s = 0.0f; int k = 0;
                for (int j = tid; j < cnt; j += 32) {
                    float v = sbuf[j];
                    if (v > tau) { s += v; k++; }
                }
                #pragma unroll
                for (int o = 16; o > 0; o >>= 1) {
                    s += __shfl_xor_sync(0xffffffffu, s, o);
                    k += __shfl_xor_sync(0xffffffffu, k, o);
                }
                tau = (s - 1.0f) / (float)k;
                if (k == prev) break;   // active set stable -> fixed point
                prev = k;
            }
            if (tid == 0) s_tau = tau;
        }
        __syncthreads();
    } else {
        // ---- Fallback: block-wide Michelot over register values ----
        float tau = thr;
        int prev = -1;
        for (int it = 0; it < D + 2; it++) {
            float s = 0.0f; int k = 0;
            float vals[PER_THREAD] = {v0.x, v0.y, v0.z, v0.w,
                                      v1.x, v1.y, v1.z, v1.w,
                                      v2.x, v2.y, v2.z, v2.w,
                                      v3.x, v3.y, v3.z, v3.w};
            #pragma unroll
            for (int i = 0; i < PER_THREAD; i++)
                if (vals[i] > tau) { s += vals[i]; k++; }
            #pragma unroll
            for (int o = 16; o > 0; o >>= 1) {
                s += __shfl_xor_sync(0xffffffffu, s, o);
                k += __shfl_xor_sync(0xffffffffu, k, o);
            }
            if (lid == 0) { sredf[tid >> 5] = s; sredk[tid >> 5] = k; }
            __syncthreads();
            if (tid == 0) {
                float S = 0.0f; int K = 0;
                #pragma unroll
                for (int w = 0; w < NWARPS; w++) { S += sredf[w]; K += sredk[w]; }
                s_tau = (S - 1.0f) / (float)K;
                s_k = K;
            }
            __syncthreads();
            tau = s_tau;
            int K = s_k;
            if (K == prev) break;
            prev = K;
        }
        __syncthreads();
    }

    // ---- Pass 3: write relu(x - tau) straight from registers ----
    const float tau = s_tau;
    v0.x = fmaxf(v0.x - tau, 0.0f); v0.y = fmaxf(v0.y - tau, 0.0f);
    v0.z = fmaxf(v0.z - tau, 0.0f); v0.w = fmaxf(v0.w - tau, 0.0f);
    v1.x = fmaxf(v1.x - tau, 0.0f); v1.y = fmaxf(v1.y - tau, 0.0f);
    v1.z = fmaxf(v1.z - tau, 0.0f); v1.w = fmaxf(v1.w - tau, 0.0f);
    v2.x = fmaxf(v2.x - tau, 0.0f); v2.y = fmaxf(v2.y - tau, 0.0f);
    v2.z = fmaxf(v2.z - tau, 0.0f); v2.w = fmaxf(v2.w - tau, 0.0f);
    v3.x = fmaxf(v3.x - tau, 0.0f); v3.y = fmaxf(v3.y - tau, 0.0f);
    v3.z = fmaxf(v3.z - tau, 0.0f); v3.w = fmaxf(v3.w - tau, 0.0f);
    xout[tid]               = v0;
    xout[tid + THREADS]     = v1;
    xout[tid + 2 * THREADS] = v2;
    xout[tid + 3 * THREADS] = v3;
}

extern "C" void kernel_launch(void* const* d_in, const int* in_sizes, int n_in,
                              void* d_out, int out_size) {
    const float* x = (const float*)d_in[0];
    float* out = (float*)d_out;
    const int rows = in_sizes[0] / D;   // 8192
    sparsemax_kernel<<<rows, THREADS>>>(x, out);
}